// round 7
// baseline (speedup 1.0000x reference)
#include <cuda_runtime.h>

#define VOCAB 87429
#define EDIM  51
#define EPG   56          // padded embedding width in GLOBAL table (14 float4)
#define EPS   60          // padded row stride in SMEM (bank-conflict-free A frags)
#define CCH   39
#define HTOK  8192
#define NJP   40          // padded j count (38 real)
#define TH    128         // h-tile per block in k1
#define NBH   (HTOK / TH) // 64
#define NCZ   13          // channel chunks of 3 (39 = 13*3)
#define SLC   (HTOK * NJP)
#define WELT  (EPG * NJP) // 2240 floats per channel per weight table

#define SEB   (TH * EPS)                      // 7680 floats per emb buffer
#define K1_SMEM_FLOATS (2 * SEB + 4 * WELT)   // 24320
#define K1_SMEM_BYTES  (K1_SMEM_FLOATS * 4)   // 97280 -> 2 blocks/SM

// scratch (device globals — no allocation allowed)
__device__ float        g_embp[VOCAB * EPG];      // padded fp32 embedding ~19.6 MB
__device__ float        g_wb  [CCH * WELT];       // weights, tf32 "big"   [c][e][j]
__device__ float        g_ws  [CCH * WELT];       // weights, tf32 "small" [c][e][j]
__device__ float        g_A   [NCZ * SLC];        // partials, layout [z][j][h] ~17 MB
__device__ unsigned int g_max5[5];

// ---------------------------------------------------------------------------
// helpers
// ---------------------------------------------------------------------------
__device__ __forceinline__ unsigned f2tf32(float x) {
    unsigned r; asm("cvt.rna.tf32.f32 %0, %1;" : "=r"(r) : "f"(x)); return r;
}
__device__ __forceinline__ void mma_tf32(float* c, unsigned a0, unsigned a1,
                                         unsigned a2, unsigned a3,
                                         unsigned b0, unsigned b1) {
    asm volatile(
        "mma.sync.aligned.m16n8k8.row.col.f32.tf32.tf32.f32 "
        "{%0,%1,%2,%3}, {%4,%5,%6,%7}, {%8,%9}, {%0,%1,%2,%3};"
        : "+f"(c[0]), "+f"(c[1]), "+f"(c[2]), "+f"(c[3])
        : "r"(a0), "r"(a1), "r"(a2), "r"(a3), "r"(b0), "r"(b1));
}
__device__ __forceinline__ void cpa16(void* dst_smem, const void* src_gmem) {
    unsigned dst = (unsigned)__cvta_generic_to_shared(dst_smem);
    asm volatile("cp.async.ca.shared.global [%0], [%1], 16;\n" :: "r"(dst), "l"(src_gmem));
}
__device__ __forceinline__ void cpa_commit() { asm volatile("cp.async.commit_group;\n"); }
__device__ __forceinline__ void cpa_wait1()  { asm volatile("cp.async.wait_group 1;\n"); }

// ---------------------------------------------------------------------------
// kernel -1: zero the 5 branch maxima
// ---------------------------------------------------------------------------
__global__ void kzero() {
    if (threadIdx.x < 5) g_max5[threadIdx.x] = 0u;
}

// ---------------------------------------------------------------------------
// kernel 0a: pad embedding table 51 -> 56 floats/row, zeros beyond EDIM
// ---------------------------------------------------------------------------
__global__ void kpad_emb(const float* __restrict__ emb) {
    int idx = blockIdx.x * blockDim.x + threadIdx.x;
    if (idx >= VOCAB * EPG) return;
    int r = idx / EPG;
    int e = idx - r * EPG;
    g_embp[idx] = (e < EDIM) ? emb[r * EDIM + e] : 0.0f;
}

// ---------------------------------------------------------------------------
// kernel 0b: pack conv weights into [c][e][j] (e-major, B-matrix layout) and
//            split each value into tf32 big + small parts (3xTF32 scheme).
// ---------------------------------------------------------------------------
__global__ void kpack_w(const float* __restrict__ w0, const float* __restrict__ w1,
                        const float* __restrict__ w2, const float* __restrict__ w3,
                        const float* __restrict__ w4) {
    int idx = blockIdx.x * blockDim.x + threadIdx.x;
    if (idx >= CCH * WELT) return;
    int c   = idx / WELT;
    int rem = idx - c * WELT;
    int e   = rem / NJP;
    int j   = rem - e * NJP;
    float v = 0.0f;
    if (j < 38 && e < EDIM) {
        const float* wp; int kk, dk;
        if      (j < 1)  { wp = w0; kk = 1;  dk = j; }
        else if (j < 3)  { wp = w1; kk = 2;  dk = j - 1; }
        else if (j < 8)  { wp = w2; kk = 5;  dk = j - 3; }
        else if (j < 18) { wp = w3; kk = 10; dk = j - 8; }
        else             { wp = w4; kk = 20; dk = j - 18; }
        v = wp[(c * kk + dk) * EDIM + e];
    }
    unsigned big = f2tf32(v);
    float    bf  = __uint_as_float(big);
    g_wb[idx] = bf;
    g_ws[idx] = __uint_as_float(f2tf32(v - bf));
}

// ---------------------------------------------------------------------------
// kernel 1: A_z[j][h] = sum_{c in chunk z} emb[tok[c,h]] . W[c][j]
//   tf32 tensor-core GEMM, 3xTF32 split.
//   128 threads = 4 warps; each warp covers 32 h x 40 j (2 m16 x 5 n8):
//   10 independent acc tiles per warp for ILP, best LDS-per-mma ratio.
//   97 KB smem -> 2 blocks/SM. 832 blocks (3 channels each) for balance.
// ---------------------------------------------------------------------------
__global__ __launch_bounds__(128, 2) void k1_dots(const int* __restrict__ tokens) {
    extern __shared__ float smem[];
    float* s_emb = smem;                          // [2][SEB]
    float* s_wb  = smem + 2 * SEB;                // [2][WELT]
    float* s_ws  = smem + 2 * SEB + 2 * WELT;     // [2][WELT]

    const int tid  = threadIdx.x;
    const int h0   = blockIdx.x * TH;
    const int z    = blockIdx.y;
    const int cbeg = z * 3;                       // nch == 3 always (39 = 13*3)

    const int w    = tid >> 5;        // warp 0..3
    const int lane = tid & 31;
    const int g    = lane >> 2;       // 0..7
    const int t    = lane & 3;        // 0..3

    // --- staging helper: channel (cbeg+CC) -> buffer B using token `tok` ---
    #define STAGE(CC, B, TOK) do {                                            \
        /* emb: 1 thread per row, 14 float4 */                                \
        {                                                                     \
            const float4* src = (const float4*)&g_embp[(TOK) * EPG];          \
            float* dst = &s_emb[(B) * SEB + tid * EPS];                       \
            _Pragma("unroll")                                                 \
            for (int q = 0; q < 14; q++)                                      \
                cpa16(dst + q * 4, src + q);                                  \
        }                                                                     \
        /* weights: 560 float4 per table */                                   \
        {                                                                     \
            const float4* sb = (const float4*)&g_wb[(cbeg + (CC)) * WELT];    \
            const float4* ss = (const float4*)&g_ws[(cbeg + (CC)) * WELT];    \
            float* db = &s_wb[(B) * WELT];                                    \
            float* ds = &s_ws[(B) * WELT];                                    \
            _Pragma("unroll")                                                 \
            for (int q = 0; q < 5; q++) {                                     \
                int idx = tid + q * 128;                                      \
                if (idx < WELT / 4) {                                         \
                    cpa16(db + idx * 4, sb + idx);                            \
                    cpa16(ds + idx * 4, ss + idx);                            \
                }                                                             \
            }                                                                 \
        }                                                                     \
    } while (0)

    float acc[2][5][4];
    #pragma unroll
    for (int mt = 0; mt < 2; mt++)
        #pragma unroll
        for (int nb = 0; nb < 5; nb++)
            #pragma unroll
            for (int r = 0; r < 4; r++) acc[mt][nb][r] = 0.0f;

    int tk1 = tokens[cbeg * HTOK + h0 + tid];
    STAGE(0, 0, tk1);
    cpa_commit();
    tk1 = tokens[(cbeg + 1) * HTOK + h0 + tid];
    int tk2 = tokens[(cbeg + 2) * HTOK + h0 + tid];

    int buf = 0;
    #pragma unroll 1
    for (int cc = 0; cc < 3; cc++) {
        if (cc == 0) STAGE(1, 1, tk1);
        else if (cc == 1) STAGE(2, 0, tk2);
        cpa_commit();
        cpa_wait1();          // buffer `buf` complete
        __syncthreads();

        const float* se = &s_emb[buf * SEB + w * 32 * EPS];
        const float* wb = &s_wb[buf * WELT];
        const float* ws = &s_ws[buf * WELT];

        #pragma unroll
        for (int ks = 0; ks < 7; ks++) {
            const int k0 = ks * 8;
            // A fragments (2 m16 tiles), on-the-fly 3xTF32 split
            unsigned ab[2][4], as_[2][4];
            #pragma unroll
            for (int mt = 0; mt < 2; mt++) {
                const float* rp = se + (mt * 16 + g) * EPS + k0 + t;
                float v0 = rp[0];
                float v1 = rp[8 * EPS];
                float v2 = rp[4];
                float v3 = rp[8 * EPS + 4];
                ab[mt][0] = f2tf32(v0); as_[mt][0] = f2tf32(v0 - __uint_as_float(ab[mt][0]));
                ab[mt][1] = f2tf32(v1); as_[mt][1] = f2tf32(v1 - __uint_as_float(ab[mt][1]));
                ab[mt][2] = f2tf32(v2); as_[mt][2] = f2tf32(v2 - __uint_as_float(ab[mt][2]));
                ab[mt][3] = f2tf32(v3); as_[mt][3] = f2tf32(v3 - __uint_as_float(ab[mt][3]));
            }
            #pragma unroll
            for (int nb = 0; nb < 5; nb++) {
                const int jo = nb * 8 + g;
                unsigned b0b = __float_as_uint(wb[(k0 + t) * NJP + jo]);
                unsigned b1b = __float_as_uint(wb[(k0 + t + 4) * NJP + jo]);
                unsigned b0s = __float_as_uint(ws[(k0 + t) * NJP + jo]);
                unsigned b1s = __float_as_uint(ws[(k0 + t + 4) * NJP + jo]);
                #pragma unroll
                for (int mt = 0; mt < 2; mt++) {
                    mma_tf32(acc[mt][nb], ab[mt][0], ab[mt][1], ab[mt][2], ab[mt][3], b0b, b1b);
                    mma_tf32(acc[mt][nb], ab[mt][0], ab[mt][1], ab[mt][2], ab[mt][3], b0s, b1s);
                    mma_tf32(acc[mt][nb], as_[mt][0], as_[mt][1], as_[mt][2], as_[mt][3], b0b, b1b);
                }
            }
        }
        __syncthreads();
        buf ^= 1;
    }
    #undef STAGE

    // epilogue: write transposed A[z][j][h]
    float* Az = &g_A[z * SLC];
    #pragma unroll
    for (int mt = 0; mt < 2; mt++) {
        const int h = h0 + w * 32 + mt * 16 + g;
        #pragma unroll
        for (int nb = 0; nb < 5; nb++) {
            const int j0 = nb * 8 + 2 * t;
            Az[j0 * HTOK + h]           = acc[mt][nb][0];
            Az[(j0 + 1) * HTOK + h]     = acc[mt][nb][1];
            Az[j0 * HTOK + h + 8]       = acc[mt][nb][2];
            Az[(j0 + 1) * HTOK + h + 8] = acc[mt][nb][3];
        }
    }
}

// ---------------------------------------------------------------------------
// kernel 2: per-(h-block, branch) max of relu(conv+b). A is [z][j][h].
//   16 lanes per h (13 real z slices), shfl-tree sum, warp max, atomicMax.
// ---------------------------------------------------------------------------
__global__ void k2_branch(const float* __restrict__ b0, const float* __restrict__ b1,
                          const float* __restrict__ b2, const float* __restrict__ b3,
                          const float* __restrict__ b4) {
    __shared__ unsigned int sm;
    const int tid = threadIdx.x;       // 256
    const int zl  = tid & 15;
    const int hl  = tid >> 4;          // 0..15
    const int br  = blockIdx.y;
    const int h   = blockIdx.x * 16 + hl;
    if (tid == 0) sm = 0u;
    __syncthreads();

    const int base[5] = {0, 1, 3, 8, 18};
    const int cnt [5] = {1, 2, 5, 10, 20};
    const int k = cnt[br];

    float y = 0.0f;
    if (zl < NCZ && h <= HTOK - k) {
        const float* Az = g_A + zl * SLC + base[br] * HTOK + h;
        #pragma unroll 5
        for (int d = 0; d < k; d++)
            y += Az[d * (HTOK + 1)];
    }
    y += __shfl_xor_sync(0xffffffffu, y, 1);
    y += __shfl_xor_sync(0xffffffffu, y, 2);
    y += __shfl_xor_sync(0xffffffffu, y, 4);
    y += __shfl_xor_sync(0xffffffffu, y, 8);

    const float* bp = (br == 0) ? b0 : (br == 1) ? b1 : (br == 2) ? b2
                    : (br == 3) ? b3 : b4;
    float val = (h <= HTOK - k) ? fmaxf(y + *bp, 0.0f) : 0.0f;
    val = fmaxf(val, __shfl_xor_sync(0xffffffffu, val, 16));
    if ((tid & 31) == 0) atomicMax(&sm, __float_as_uint(val));
    __syncthreads();
    if (tid == 0) atomicMax(&g_max5[br], sm);
}

// ---------------------------------------------------------------------------
// kernel 3: 5 -> 8 linear, relu, softmax -> out[8]
// ---------------------------------------------------------------------------
__global__ void k3_head(const float* __restrict__ lin_w, const float* __restrict__ lin_b,
                        float* __restrict__ out) {
    if (threadIdx.x != 0 || blockIdx.x != 0) return;
    float f[5];
    #pragma unroll
    for (int i = 0; i < 5; i++) f[i] = __uint_as_float(g_max5[i]);
    float lg[8], mx = -1e30f;
    #pragma unroll
    for (int o = 0; o < 8; o++) {
        float s = lin_b[o];
        #pragma unroll
        for (int i = 0; i < 5; i++) s += lin_w[o * 5 + i] * f[i];
        s = fmaxf(s, 0.0f);
        lg[o] = s;
        mx = fmaxf(mx, s);
    }
    float den = 0.0f;
    #pragma unroll
    for (int o = 0; o < 8; o++) { lg[o] = expf(lg[o] - mx); den += lg[o]; }
    #pragma unroll
    for (int o = 0; o < 8; o++) out[o] = lg[o] / den;
}

// ---------------------------------------------------------------------------
extern "C" void kernel_launch(void* const* d_in, const int* in_sizes, int n_in,
                              void* d_out, int out_size) {
    const int*   tokens = (const int*)  d_in[0];
    const float* emb    = (const float*)d_in[1];
    const float* lin_w  = (const float*)d_in[2];
    const float* lin_b  = (const float*)d_in[3];
    const float* w0     = (const float*)d_in[4];
    const float* b0     = (const float*)d_in[5];
    const float* w1     = (const float*)d_in[6];
    const float* b1     = (const float*)d_in[7];
    const float* w2     = (const float*)d_in[8];
    const float* b2     = (const float*)d_in[9];
    const float* w3     = (const float*)d_in[10];
    const float* b3     = (const float*)d_in[11];
    const float* w4     = (const float*)d_in[12];
    const float* b4     = (const float*)d_in[13];
    float* out = (float*)d_out;

    static int smem_set = 0;
    if (!smem_set) {
        cudaFuncSetAttribute(k1_dots, cudaFuncAttributeMaxDynamicSharedMemorySize,
                             K1_SMEM_BYTES);
        smem_set = 1;
    }

    kzero   <<<1, 32>>>();
    kpad_emb<<<(VOCAB * EPG + 255) / 256, 256>>>(emb);
    kpack_w <<<(CCH * WELT + 255) / 256, 256>>>(w0, w1, w2, w3, w4);
    k1_dots <<<dim3(NBH, NCZ), 128, K1_SMEM_BYTES>>>(tokens);
    k2_branch<<<dim3(HTOK / 16, 5), 256>>>(b0, b1, b2, b3, b4);
    k3_head <<<1, 32>>>(lin_w, lin_b, out);
}

// round 8
// speedup vs baseline: 1.1655x; 1.1655x over previous
#include <cuda_runtime.h>

#define VOCAB 87429
#define EDIM  51
#define EPG   56          // padded embedding width in GLOBAL table (14 float4)
#define EPS   60          // padded row stride in SMEM (bank-conflict-free A frags)
#define CCH   39
#define HTOK  8192
#define NJP   40          // padded j count (38 real)
#define TH    256         // h-tile per block in k1
#define NBH   (HTOK / TH) // 32
#define NCZ   13          // channel chunks of 3 (39 = 13*3)
#define SLC   (HTOK * NJP)
#define WELT  (EPG * NJP) // 2240 floats per channel per weight table

#define SEB   (TH * EPS)                      // 15360 floats (single emb buffer)
#define K1_SMEM_FLOATS (SEB + 4 * WELT)       // 24320
#define K1_SMEM_BYTES  (K1_SMEM_FLOATS * 4)   // 97280 -> 2 blocks/SM (16 warps)

#define TF32_MASK 0xFFFFE000u

// scratch (device globals — no allocation allowed)
__device__ float        g_embp[VOCAB * EPG];      // padded fp32 embedding ~19.6 MB
__device__ float        g_wb  [CCH * WELT];       // weights, tf32 "big"   [c][e][j]
__device__ float        g_ws  [CCH * WELT];       // weights, tf32 "small" [c][e][j]
__device__ float        g_A   [NCZ * SLC];        // partials, layout [z][j][h]
__device__ float        g_Asum[SLC];              // reduced projections [j][h]
__device__ unsigned int g_max5[5];

// ---------------------------------------------------------------------------
// helpers
// ---------------------------------------------------------------------------
__device__ __forceinline__ unsigned f2tf32(float x) {
    unsigned r; asm("cvt.rna.tf32.f32 %0, %1;" : "=r"(r) : "f"(x)); return r;
}
__device__ __forceinline__ void mma_tf32(float* c, unsigned a0, unsigned a1,
                                         unsigned a2, unsigned a3,
                                         unsigned b0, unsigned b1) {
    asm volatile(
        "mma.sync.aligned.m16n8k8.row.col.f32.tf32.tf32.f32 "
        "{%0,%1,%2,%3}, {%4,%5,%6,%7}, {%8,%9}, {%0,%1,%2,%3};"
        : "+f"(c[0]), "+f"(c[1]), "+f"(c[2]), "+f"(c[3])
        : "r"(a0), "r"(a1), "r"(a2), "r"(a3), "r"(b0), "r"(b1));
}
__device__ __forceinline__ void cpa16(void* dst_smem, const void* src_gmem) {
    unsigned dst = (unsigned)__cvta_generic_to_shared(dst_smem);
    asm volatile("cp.async.ca.shared.global [%0], [%1], 16;\n" :: "r"(dst), "l"(src_gmem));
}
__device__ __forceinline__ void cpa_commit() { asm volatile("cp.async.commit_group;\n"); }
__device__ __forceinline__ void cpa_wait1()  { asm volatile("cp.async.wait_group 1;\n"); }
__device__ __forceinline__ void cpa_wait0()  { asm volatile("cp.async.wait_group 0;\n"); }

// ---------------------------------------------------------------------------
// kernel -1: zero the 5 branch maxima (also keeps k1 at ncu's profiled slot)
// ---------------------------------------------------------------------------
__global__ void kzero() {
    if (threadIdx.x < 5) g_max5[threadIdx.x] = 0u;
}

// ---------------------------------------------------------------------------
// kernel 0a: pad embedding table 51 -> 56 floats/row, zeros beyond EDIM
// ---------------------------------------------------------------------------
__global__ void kpad_emb(const float* __restrict__ emb) {
    int idx = blockIdx.x * blockDim.x + threadIdx.x;
    if (idx >= VOCAB * EPG) return;
    int r = idx / EPG;
    int e = idx - r * EPG;
    g_embp[idx] = (e < EDIM) ? emb[r * EDIM + e] : 0.0f;
}

// ---------------------------------------------------------------------------
// kernel 0b: pack conv weights into [c][e][j] and split big/small (3xTF32)
// ---------------------------------------------------------------------------
__global__ void kpack_w(const float* __restrict__ w0, const float* __restrict__ w1,
                        const float* __restrict__ w2, const float* __restrict__ w3,
                        const float* __restrict__ w4) {
    int idx = blockIdx.x * blockDim.x + threadIdx.x;
    if (idx >= CCH * WELT) return;
    int c   = idx / WELT;
    int rem = idx - c * WELT;
    int e   = rem / NJP;
    int j   = rem - e * NJP;
    float v = 0.0f;
    if (j < 38 && e < EDIM) {
        const float* wp; int kk, dk;
        if      (j < 1)  { wp = w0; kk = 1;  dk = j; }
        else if (j < 3)  { wp = w1; kk = 2;  dk = j - 1; }
        else if (j < 8)  { wp = w2; kk = 5;  dk = j - 3; }
        else if (j < 18) { wp = w3; kk = 10; dk = j - 8; }
        else             { wp = w4; kk = 20; dk = j - 18; }
        v = wp[(c * kk + dk) * EDIM + e];
    }
    unsigned big = f2tf32(v);
    float    bf  = __uint_as_float(big);
    g_wb[idx] = bf;
    g_ws[idx] = __uint_as_float(f2tf32(v - bf));
}

// ---------------------------------------------------------------------------
// kernel 1: A_z[j][h] = sum_{c in chunk z} emb[tok[c,h]] . W[c][j]
//   tf32 mma, 3xTF32 via LOP3 mask split (no cvt in the hot chain).
//   256 threads = 8 warps; warp covers 32 h x 40 j (2 m16 x 5 n8) -> 10 tiles.
//   Single-buffer emb + double-buffer weights = 97 KB -> 2 blocks/SM.
// ---------------------------------------------------------------------------
__global__ __launch_bounds__(256, 2) void k1_dots(const int* __restrict__ tokens) {
    extern __shared__ float smem[];
    float* s_emb = smem;                      // [SEB]
    float* s_wb  = smem + SEB;                // [2][WELT]
    float* s_ws  = smem + SEB + 2 * WELT;     // [2][WELT]

    const int tid  = threadIdx.x;
    const int h0   = blockIdx.x * TH;
    const int z    = blockIdx.y;
    const int cbeg = z * 3;                   // always 3 channels (39 = 13*3)

    const int w    = tid >> 5;        // warp 0..7
    const int lane = tid & 31;
    const int g    = lane >> 2;       // 0..7
    const int t    = lane & 3;        // 0..3

    const int tk0 = tokens[(cbeg + 0) * HTOK + h0 + tid];
    const int tk1 = tokens[(cbeg + 1) * HTOK + h0 + tid];
    const int tk2 = tokens[(cbeg + 2) * HTOK + h0 + tid];

    #define STAGE_W(CC, B) do {                                               \
        const float4* sb = (const float4*)&g_wb[(cbeg + (CC)) * WELT];        \
        const float4* ss = (const float4*)&g_ws[(cbeg + (CC)) * WELT];        \
        float* db = &s_wb[(B) * WELT];                                        \
        float* ds = &s_ws[(B) * WELT];                                        \
        _Pragma("unroll")                                                     \
        for (int q = 0; q < 3; q++) {                                         \
            int idx = tid + q * 256;                                          \
            if (idx < WELT / 4) {                                             \
                cpa16(db + idx * 4, sb + idx);                                \
                cpa16(ds + idx * 4, ss + idx);                                \
            }                                                                 \
        }                                                                     \
    } while (0)

    #define STAGE_E(TOK) do {                                                 \
        const float4* src = (const float4*)&g_embp[(TOK) * EPG];              \
        float* dst = &s_emb[tid * EPS];                                       \
        _Pragma("unroll")                                                     \
        for (int q = 0; q < 14; q++)                                          \
            cpa16(dst + q * 4, src + q);                                      \
    } while (0)

    float acc[2][5][4];
    #pragma unroll
    for (int mt = 0; mt < 2; mt++)
        #pragma unroll
        for (int nb = 0; nb < 5; nb++)
            #pragma unroll
            for (int r = 0; r < 4; r++) acc[mt][nb][r] = 0.0f;

    // one compute pass over the staged channel (weights buffer BW)
    #define COMPUTE(BW) do {                                                  \
        const float* se = &s_emb[w * 32 * EPS];                               \
        const float* wb = &s_wb[(BW) * WELT];                                 \
        const float* ws = &s_ws[(BW) * WELT];                                 \
        _Pragma("unroll")                                                     \
        for (int ks = 0; ks < 7; ks++) {                                      \
            const int k0 = ks * 8;                                            \
            unsigned ab[2][4], as_[2][4];                                     \
            _Pragma("unroll")                                                 \
            for (int mt = 0; mt < 2; mt++) {                                  \
                const float* rp = se + (mt * 16 + g) * EPS + k0 + t;          \
                float v0 = rp[0];                                             \
                float v1 = rp[8 * EPS];                                       \
                float v2 = rp[4];                                             \
                float v3 = rp[8 * EPS + 4];                                   \
                ab[mt][0] = __float_as_uint(v0) & TF32_MASK;                  \
                ab[mt][1] = __float_as_uint(v1) & TF32_MASK;                  \
                ab[mt][2] = __float_as_uint(v2) & TF32_MASK;                  \
                ab[mt][3] = __float_as_uint(v3) & TF32_MASK;                  \
                as_[mt][0] = __float_as_uint(v0 - __uint_as_float(ab[mt][0]));\
                as_[mt][1] = __float_as_uint(v1 - __uint_as_float(ab[mt][1]));\
                as_[mt][2] = __float_as_uint(v2 - __uint_as_float(ab[mt][2]));\
                as_[mt][3] = __float_as_uint(v3 - __uint_as_float(ab[mt][3]));\
            }                                                                 \
            _Pragma("unroll")                                                 \
            for (int nb = 0; nb < 5; nb++) {                                  \
                const int jo = nb * 8 + g;                                    \
                unsigned b0b = __float_as_uint(wb[(k0 + t) * NJP + jo]);      \
                unsigned b1b = __float_as_uint(wb[(k0 + t + 4) * NJP + jo]);  \
                unsigned b0s = __float_as_uint(ws[(k0 + t) * NJP + jo]);      \
                unsigned b1s = __float_as_uint(ws[(k0 + t + 4) * NJP + jo]);  \
                _Pragma("unroll")                                             \
                for (int mt = 0; mt < 2; mt++) {                              \
                    mma_tf32(acc[mt][nb], ab[mt][0], ab[mt][1], ab[mt][2],    \
                             ab[mt][3], b0b, b1b);                            \
                    mma_tf32(acc[mt][nb], ab[mt][0], ab[mt][1], ab[mt][2],    \
                             ab[mt][3], b0s, b1s);                            \
                    mma_tf32(acc[mt][nb], as_[mt][0], as_[mt][1], as_[mt][2], \
                             as_[mt][3], b0b, b1b);                           \
                }                                                             \
            }                                                                 \
        }                                                                     \
    } while (0)

    // pipeline: weights one-ahead (double buffer), emb single buffer
    STAGE_W(0, 0); STAGE_E(tk0); cpa_commit();   // G0 = {w0, emb0}
    STAGE_W(1, 1); cpa_commit();                 // G1 = {w1}

    cpa_wait1();                 // G0 done
    __syncthreads();
    COMPUTE(0);                  // channel 0
    __syncthreads();
    STAGE_E(tk1); cpa_commit();  // G2 = {emb1}
    STAGE_W(2, 0); cpa_commit(); // G3 = {w2}

    cpa_wait1();                 // G1, G2 done
    __syncthreads();
    COMPUTE(1);                  // channel 1
    __syncthreads();
    STAGE_E(tk2); cpa_commit();  // G4 = {emb2}

    cpa_wait0();                 // G3, G4 done
    __syncthreads();
    COMPUTE(0);                  // channel 2

    #undef STAGE_W
    #undef STAGE_E
    #undef COMPUTE

    // epilogue: write transposed A[z][j][h]
    float* Az = &g_A[z * SLC];
    #pragma unroll
    for (int mt = 0; mt < 2; mt++) {
        const int h = h0 + w * 32 + mt * 16 + g;
        #pragma unroll
        for (int nb = 0; nb < 5; nb++) {
            const int j0 = nb * 8 + 2 * t;
            Az[j0 * HTOK + h]           = acc[mt][nb][0];
            Az[(j0 + 1) * HTOK + h]     = acc[mt][nb][1];
            Az[j0 * HTOK + h + 8]       = acc[mt][nb][2];
            Az[(j0 + 1) * HTOK + h + 8] = acc[mt][nb][3];
        }
    }
}

// ---------------------------------------------------------------------------
// kernel 1b: reduce the 13 partial slices -> A_sum[j][h] (L2-hot)
// ---------------------------------------------------------------------------
__global__ void k1_reduce() {
    int idx = blockIdx.x * 256 + threadIdx.x;
    if (idx >= SLC) return;
    float s = 0.0f;
    #pragma unroll
    for (int z = 0; z < NCZ; z++) s += g_A[z * SLC + idx];
    g_Asum[idx] = s;
}

// ---------------------------------------------------------------------------
// kernel 2: per-(h-block, branch) max of relu(conv+b) on A_sum[j][h]
// ---------------------------------------------------------------------------
__global__ void k2_branch(const float* __restrict__ b0, const float* __restrict__ b1,
                          const float* __restrict__ b2, const float* __restrict__ b3,
                          const float* __restrict__ b4) {
    __shared__ unsigned int sm;
    const int tid = threadIdx.x;       // 256
    const int br  = blockIdx.y;
    const int h   = blockIdx.x * 256 + tid;
    if (tid == 0) sm = 0u;
    __syncthreads();

    const int base[5] = {0, 1, 3, 8, 18};
    const int cnt [5] = {1, 2, 5, 10, 20};
    const int k = cnt[br];

    float val = 0.0f;
    if (h <= HTOK - k) {
        float y = 0.0f;
        const float* Ap = g_Asum + base[br] * HTOK + h;
        #pragma unroll 5
        for (int d = 0; d < k; d++)
            y += Ap[d * (HTOK + 1)];
        const float* bp = (br == 0) ? b0 : (br == 1) ? b1 : (br == 2) ? b2
                        : (br == 3) ? b3 : b4;
        val = fmaxf(y + *bp, 0.0f);
    }
    #pragma unroll
    for (int off = 16; off; off >>= 1)
        val = fmaxf(val, __shfl_xor_sync(0xffffffffu, val, off));
    if ((tid & 31) == 0) atomicMax(&sm, __float_as_uint(val));
    __syncthreads();
    if (tid == 0) atomicMax(&g_max5[br], sm);
}

// ---------------------------------------------------------------------------
// kernel 3: 5 -> 8 linear, relu, softmax -> out[8]
// ---------------------------------------------------------------------------
__global__ void k3_head(const float* __restrict__ lin_w, const float* __restrict__ lin_b,
                        float* __restrict__ out) {
    if (threadIdx.x != 0 || blockIdx.x != 0) return;
    float f[5];
    #pragma unroll
    for (int i = 0; i < 5; i++) f[i] = __uint_as_float(g_max5[i]);
    float lg[8], mx = -1e30f;
    #pragma unroll
    for (int o = 0; o < 8; o++) {
        float s = lin_b[o];
        #pragma unroll
        for (int i = 0; i < 5; i++) s += lin_w[o * 5 + i] * f[i];
        s = fmaxf(s, 0.0f);
        lg[o] = s;
        mx = fmaxf(mx, s);
    }
    float den = 0.0f;
    #pragma unroll
    for (int o = 0; o < 8; o++) { lg[o] = expf(lg[o] - mx); den += lg[o]; }
    #pragma unroll
    for (int o = 0; o < 8; o++) out[o] = lg[o] / den;
}

// ---------------------------------------------------------------------------
extern "C" void kernel_launch(void* const* d_in, const int* in_sizes, int n_in,
                              void* d_out, int out_size) {
    const int*   tokens = (const int*)  d_in[0];
    const float* emb    = (const float*)d_in[1];
    const float* lin_w  = (const float*)d_in[2];
    const float* lin_b  = (const float*)d_in[3];
    const float* w0     = (const float*)d_in[4];
    const float* b0     = (const float*)d_in[5];
    const float* w1     = (const float*)d_in[6];
    const float* b1     = (const float*)d_in[7];
    const float* w2     = (const float*)d_in[8];
    const float* b2     = (const float*)d_in[9];
    const float* w3     = (const float*)d_in[10];
    const float* b3     = (const float*)d_in[11];
    const float* w4     = (const float*)d_in[12];
    const float* b4     = (const float*)d_in[13];
    float* out = (float*)d_out;

    static int smem_set = 0;
    if (!smem_set) {
        cudaFuncSetAttribute(k1_dots, cudaFuncAttributeMaxDynamicSharedMemorySize,
                             K1_SMEM_BYTES);
        smem_set = 1;
    }

    kzero    <<<1, 32>>>();
    kpad_emb <<<(VOCAB * EPG + 255) / 256, 256>>>(emb);
    kpack_w  <<<(CCH * WELT + 255) / 256, 256>>>(w0, w1, w2, w3, w4);
    k1_dots  <<<dim3(NBH, NCZ), 256, K1_SMEM_BYTES>>>(tokens);
    k1_reduce<<<(SLC + 255) / 256, 256>>>();
    k2_branch<<<dim3(HTOK / 256, 5), 256>>>(b0, b1, b2, b3, b4);
    k3_head  <<<1, 32>>>(lin_w, lin_b, out);
}

// round 10
// speedup vs baseline: 1.1686x; 1.0026x over previous
#include <cuda_runtime.h>

#define VOCAB 87429
#define EDIM  51
#define EPG   56          // padded embedding width in GLOBAL table (14 float4)
#define EPS   60          // padded row stride in SMEM (bank-conflict-free A frags)
#define CCH   39
#define HTOK  8192
#define NJP   40          // padded j count (38 real)
#define TH    256         // h-tile per block in k1
#define NBH   (HTOK / TH) // 32
#define NCZ   13          // channel chunks of 3 (39 = 13*3)
#define SLC   (HTOK * NJP)
#define WELT  (EPG * NJP) // 2240 floats per channel per weight table

#define SEB   (TH * EPS)                      // 15360 floats (single emb buffer)
#define K1_SMEM_FLOATS (SEB + 4 * WELT)       // 24320
#define K1_SMEM_BYTES  (K1_SMEM_FLOATS * 4)   // 97280 -> 2 blocks/SM

#define TF32_MASK 0xFFFFE000u

// scratch (device globals — no allocation allowed)
__device__ float        g_embp[VOCAB * EPG];      // padded fp32 embedding ~19.6 MB
__device__ float        g_wb  [CCH * WELT];       // weights, tf32 "big"   [c][e][j]
__device__ float        g_ws  [CCH * WELT];       // weights, tf32 "small" [c][e][j]
__device__ float        g_A   [NCZ * SLC];        // partials, layout [z][j][h]
__device__ float        g_Asum[SLC];              // reduced projections [j][h]
__device__ unsigned int g_max5[5];

// ---------------------------------------------------------------------------
// helpers
// ---------------------------------------------------------------------------
__device__ __forceinline__ unsigned f2tf32(float x) {
    unsigned r; asm("cvt.rna.tf32.f32 %0, %1;" : "=r"(r) : "f"(x)); return r;
}
__device__ __forceinline__ void mma_tf32(float* c, unsigned a0, unsigned a1,
                                         unsigned a2, unsigned a3,
                                         unsigned b0, unsigned b1) {
    asm volatile(
        "mma.sync.aligned.m16n8k8.row.col.f32.tf32.tf32.f32 "
        "{%0,%1,%2,%3}, {%4,%5,%6,%7}, {%8,%9}, {%0,%1,%2,%3};"
        : "+f"(c[0]), "+f"(c[1]), "+f"(c[2]), "+f"(c[3])
        : "r"(a0), "r"(a1), "r"(a2), "r"(a3), "r"(b0), "r"(b1));
}
__device__ __forceinline__ void cpa16(void* dst_smem, const void* src_gmem) {
    unsigned dst = (unsigned)__cvta_generic_to_shared(dst_smem);
    asm volatile("cp.async.ca.shared.global [%0], [%1], 16;\n" :: "r"(dst), "l"(src_gmem));
}
__device__ __forceinline__ void cpa_commit() { asm volatile("cp.async.commit_group;\n"); }
__device__ __forceinline__ void cpa_wait1()  { asm volatile("cp.async.wait_group 1;\n"); }
__device__ __forceinline__ void cpa_wait0()  { asm volatile("cp.async.wait_group 0;\n"); }

// ---------------------------------------------------------------------------
// kernel -1: zero the 5 branch maxima (also keeps k1 at ncu's profiled slot)
// ---------------------------------------------------------------------------
__global__ void kzero() {
    if (threadIdx.x < 5) g_max5[threadIdx.x] = 0u;
}

// ---------------------------------------------------------------------------
// kernel 0a: pad embedding table 51 -> 56 floats/row, zeros beyond EDIM
// ---------------------------------------------------------------------------
__global__ void kpad_emb(const float* __restrict__ emb) {
    int idx = blockIdx.x * blockDim.x + threadIdx.x;
    if (idx >= VOCAB * EPG) return;
    int r = idx / EPG;
    int e = idx - r * EPG;
    g_embp[idx] = (e < EDIM) ? emb[r * EDIM + e] : 0.0f;
}

// ---------------------------------------------------------------------------
// kernel 0b: pack conv weights into [c][e][j] and split big/small (3xTF32)
// ---------------------------------------------------------------------------
__global__ void kpack_w(const float* __restrict__ w0, const float* __restrict__ w1,
                        const float* __restrict__ w2, const float* __restrict__ w3,
                        const float* __restrict__ w4) {
    int idx = blockIdx.x * blockDim.x + threadIdx.x;
    if (idx >= CCH * WELT) return;
    int c   = idx / WELT;
    int rem = idx - c * WELT;
    int e   = rem / NJP;
    int j   = rem - e * NJP;
    float v = 0.0f;
    if (j < 38 && e < EDIM) {
        const float* wp; int kk, dk;
        if      (j < 1)  { wp = w0; kk = 1;  dk = j; }
        else if (j < 3)  { wp = w1; kk = 2;  dk = j - 1; }
        else if (j < 8)  { wp = w2; kk = 5;  dk = j - 3; }
        else if (j < 18) { wp = w3; kk = 10; dk = j - 8; }
        else             { wp = w4; kk = 20; dk = j - 18; }
        v = wp[(c * kk + dk) * EDIM + e];
    }
    unsigned big = f2tf32(v);
    float    bf  = __uint_as_float(big);
    g_wb[idx] = bf;
    g_ws[idx] = __uint_as_float(f2tf32(v - bf));
}

// ---------------------------------------------------------------------------
// kernel 1: A_z[j][h] = sum_{c in chunk z} emb[tok[c,h]] . W[c][j]
//   tf32 mma, 3xTF32 via LOP3 mask split.
//   128 threads = 4 warps; each warp covers 64 h x 40 j (4 m16 x 5 n8):
//   20 independent acc tiles; B-fragment LDS amortized over 2x more mma.
//   Single-buffer emb + double-buffer weights = 97 KB -> 2 blocks/SM.
// ---------------------------------------------------------------------------
__global__ __launch_bounds__(128, 2) void k1_dots(const int* __restrict__ tokens) {
    extern __shared__ float smem[];
    float* s_emb = smem;                      // [SEB]
    float* s_wb  = smem + SEB;                // [2][WELT]
    float* s_ws  = smem + SEB + 2 * WELT;     // [2][WELT]

    const int tid  = threadIdx.x;
    const int h0   = blockIdx.x * TH;
    const int z    = blockIdx.y;
    const int cbeg = z * 3;                   // always 3 channels (39 = 13*3)

    const int w    = tid >> 5;        // warp 0..3
    const int lane = tid & 31;
    const int g    = lane >> 2;       // 0..7
    const int t    = lane & 3;        // 0..3

    // staging: each thread handles 2 emb rows (tid, tid+128)
    int tkA[3], tkB[3];
    #pragma unroll
    for (int i = 0; i < 3; i++) {
        tkA[i] = tokens[(cbeg + i) * HTOK + h0 + tid];
        tkB[i] = tokens[(cbeg + i) * HTOK + h0 + tid + 128];
    }

    #define STAGE_W(CC, B) do {                                               \
        const float4* sb = (const float4*)&g_wb[(cbeg + (CC)) * WELT];        \
        const float4* ss = (const float4*)&g_ws[(cbeg + (CC)) * WELT];        \
        float* db = &s_wb[(B) * WELT];                                        \
        float* ds = &s_ws[(B) * WELT];                                        \
        _Pragma("unroll")                                                     \
        for (int q = 0; q < 5; q++) {                                         \
            int idx = tid + q * 128;                                          \
            if (idx < WELT / 4) {                                             \
                cpa16(db + idx * 4, sb + idx);                                \
                cpa16(ds + idx * 4, ss + idx);                                \
            }                                                                 \
        }                                                                     \
    } while (0)

    #define STAGE_E(CC) do {                                                  \
        const float4* srcA = (const float4*)&g_embp[tkA[(CC)] * EPG];         \
        const float4* srcB = (const float4*)&g_embp[tkB[(CC)] * EPG];         \
        float* dstA = &s_emb[tid * EPS];                                      \
        float* dstB = &s_emb[(tid + 128) * EPS];                              \
        _Pragma("unroll")                                                     \
        for (int q = 0; q < 14; q++) {                                        \
            cpa16(dstA + q * 4, srcA + q);                                    \
            cpa16(dstB + q * 4, srcB + q);                                    \
        }                                                                     \
    } while (0)

    float acc[4][5][4];
    #pragma unroll
    for (int mt = 0; mt < 4; mt++)
        #pragma unroll
        for (int nb = 0; nb < 5; nb++)
            #pragma unroll
            for (int r = 0; r < 4; r++) acc[mt][nb][r] = 0.0f;

    // one compute pass over the staged channel (weights buffer BW)
    #define COMPUTE(BW) do {                                                  \
        const float* se = &s_emb[w * 64 * EPS];                               \
        const float* wb = &s_wb[(BW) * WELT];                                 \
        const float* ws = &s_ws[(BW) * WELT];                                 \
        _Pragma("unroll")                                                     \
        for (int ks = 0; ks < 7; ks++) {                                      \
            const int k0 = ks * 8;                                            \
            unsigned ab[4][4], as_[4][4];                                     \
            _Pragma("unroll")                                                 \
            for (int mt = 0; mt < 4; mt++) {                                  \
                const float* rp = se + (mt * 16 + g) * EPS + k0 + t;          \
                float v0 = rp[0];                                             \
                float v1 = rp[8 * EPS];                                       \
                float v2 = rp[4];                                             \
                float v3 = rp[8 * EPS + 4];                                   \
                ab[mt][0] = __float_as_uint(v0) & TF32_MASK;                  \
                ab[mt][1] = __float_as_uint(v1) & TF32_MASK;                  \
                ab[mt][2] = __float_as_uint(v2) & TF32_MASK;                  \
                ab[mt][3] = __float_as_uint(v3) & TF32_MASK;                  \
                as_[mt][0] = __float_as_uint(v0 - __uint_as_float(ab[mt][0]));\
                as_[mt][1] = __float_as_uint(v1 - __uint_as_float(ab[mt][1]));\
                as_[mt][2] = __float_as_uint(v2 - __uint_as_float(ab[mt][2]));\
                as_[mt][3] = __float_as_uint(v3 - __uint_as_float(ab[mt][3]));\
            }                                                                 \
            _Pragma("unroll")                                                 \
            for (int nb = 0; nb < 5; nb++) {                                  \
                const int jo = nb * 8 + g;                                    \
                unsigned b0b = __float_as_uint(wb[(k0 + t) * NJP + jo]);      \
                unsigned b1b = __float_as_uint(wb[(k0 + t + 4) * NJP + jo]);  \
                unsigned b0s = __float_as_uint(ws[(k0 + t) * NJP + jo]);      \
                unsigned b1s = __float_as_uint(ws[(k0 + t + 4) * NJP + jo]);  \
                _Pragma("unroll")                                             \
                for (int mt = 0; mt < 4; mt++) {                              \
                    mma_tf32(acc[mt][nb], ab[mt][0], ab[mt][1], ab[mt][2],    \
                             ab[mt][3], b0b, b1b);                            \
                    mma_tf32(acc[mt][nb], ab[mt][0], ab[mt][1], ab[mt][2],    \
                             ab[mt][3], b0s, b1s);                            \
                    mma_tf32(acc[mt][nb], as_[mt][0], as_[mt][1], as_[mt][2], \
                             as_[mt][3], b0b, b1b);                           \
                }                                                             \
            }                                                                 \
        }                                                                     \
    } while (0)

    // pipeline: weights one-ahead (double buffer), emb single buffer
    STAGE_W(0, 0); STAGE_E(0); cpa_commit();   // G0 = {w0, emb0}
    STAGE_W(1, 1); cpa_commit();               // G1 = {w1}

    cpa_wait1();                 // G0 done
    __syncthreads();
    COMPUTE(0);                  // channel 0
    __syncthreads();
    STAGE_E(1); cpa_commit();    // G2 = {emb1}
    STAGE_W(2, 0); cpa_commit(); // G3 = {w2}

    cpa_wait1();                 // G1, G2 done
    __syncthreads();
    COMPUTE(1);                  // channel 1
    __syncthreads();
    STAGE_E(2); cpa_commit();    // G4 = {emb2}

    cpa_wait0();                 // G3, G4 done
    __syncthreads();
    COMPUTE(0);                  // channel 2

    #undef STAGE_W
    #undef STAGE_E
    #undef COMPUTE

    // epilogue: write transposed A[z][j][h]
    float* Az = &g_A[z * SLC];
    #pragma unroll
    for (int mt = 0; mt < 4; mt++) {
        const int h = h0 + w * 64 + mt * 16 + g;
        #pragma unroll
        for (int nb = 0; nb < 5; nb++) {
            const int j0 = nb * 8 + 2 * t;
            Az[j0 * HTOK + h]           = acc[mt][nb][0];
            Az[(j0 + 1) * HTOK + h]     = acc[mt][nb][1];
            Az[j0 * HTOK + h + 8]       = acc[mt][nb][2];
            Az[(j0 + 1) * HTOK + h + 8] = acc[mt][nb][3];
        }
    }
}

// ---------------------------------------------------------------------------
// kernel 1b: reduce the 13 partial slices -> A_sum[j][h] (L2-hot)
// ---------------------------------------------------------------------------
__global__ void k1_reduce() {
    int idx = blockIdx.x * 256 + threadIdx.x;
    if (idx >= SLC) return;
    float s = 0.0f;
    #pragma unroll
    for (int z = 0; z < NCZ; z++) s += g_A[z * SLC + idx];
    g_Asum[idx] = s;
}

// ---------------------------------------------------------------------------
// kernel 2: per-(h-block, branch) max of relu(conv+b) on A_sum[j][h]
// ---------------------------------------------------------------------------
__global__ void k2_branch(const float* __restrict__ b0, const float* __restrict__ b1,
                          const float* __restrict__ b2, const float* __restrict__ b3,
                          const float* __restrict__ b4) {
    __shared__ unsigned int sm;
    const int tid = threadIdx.x;       // 256
    const int br  = blockIdx.y;
    const int h   = blockIdx.x * 256 + tid;
    if (tid == 0) sm = 0u;
    __syncthreads();

    const int base[5] = {0, 1, 3, 8, 18};
    const int cnt [5] = {1, 2, 5, 10, 20};
    const int k = cnt[br];

    float val = 0.0f;
    if (h <= HTOK - k) {
        float y = 0.0f;
        const float* Ap = g_Asum + base[br] * HTOK + h;
        #pragma unroll 5
        for (int d = 0; d < k; d++)
            y += Ap[d * (HTOK + 1)];
        const float* bp = (br == 0) ? b0 : (br == 1) ? b1 : (br == 2) ? b2
                        : (br == 3) ? b3 : b4;
        val = fmaxf(y + *bp, 0.0f);
    }
    #pragma unroll
    for (int off = 16; off; off >>= 1)
        val = fmaxf(val, __shfl_xor_sync(0xffffffffu, val, off));
    if ((tid & 31) == 0) atomicMax(&sm, __float_as_uint(val));
    __syncthreads();
    if (tid == 0) atomicMax(&g_max5[br], sm);
}

// ---------------------------------------------------------------------------
// kernel 3: 5 -> 8 linear, relu, softmax -> out[8]
// ---------------------------------------------------------------------------
__global__ void k3_head(const float* __restrict__ lin_w, const float* __restrict__ lin_b,
                        float* __restrict__ out) {
    if (threadIdx.x != 0 || blockIdx.x != 0) return;
    float f[5];
    #pragma unroll
    for (int i = 0; i < 5; i++) f[i] = __uint_as_float(g_max5[i]);
    float lg[8], mx = -1e30f;
    #pragma unroll
    for (int o = 0; o < 8; o++) {
        float s = lin_b[o];
        #pragma unroll
        for (int i = 0; i < 5; i++) s += lin_w[o * 5 + i] * f[i];
        s = fmaxf(s, 0.0f);
        lg[o] = s;
        mx = fmaxf(mx, s);
    }
    float den = 0.0f;
    #pragma unroll
    for (int o = 0; o < 8; o++) { lg[o] = expf(lg[o] - mx); den += lg[o]; }
    #pragma unroll
    for (int o = 0; o < 8; o++) out[o] = lg[o] / den;
}

// ---------------------------------------------------------------------------
extern "C" void kernel_launch(void* const* d_in, const int* in_sizes, int n_in,
                              void* d_out, int out_size) {
    const int*   tokens = (const int*)  d_in[0];
    const float* emb    = (const float*)d_in[1];
    const float* lin_w  = (const float*)d_in[2];
    const float* lin_b  = (const float*)d_in[3];
    const float* w0     = (const float*)d_in[4];
    const float* b0     = (const float*)d_in[5];
    const float* w1     = (const float*)d_in[6];
    const float* b1     = (const float*)d_in[7];
    const float* w2     = (const float*)d_in[8];
    const float* b2     = (const float*)d_in[9];
    const float* w3     = (const float*)d_in[10];
    const float* b3     = (const float*)d_in[11];
    const float* w4     = (const float*)d_in[12];
    const float* b4     = (const float*)d_in[13];
    float* out = (float*)d_out;

    static int smem_set = 0;
    if (!smem_set) {
        cudaFuncSetAttribute(k1_dots, cudaFuncAttributeMaxDynamicSharedMemorySize,
                             K1_SMEM_BYTES);
        smem_set = 1;
    }

    kzero    <<<1, 32>>>();
    kpad_emb <<<(VOCAB * EPG + 255) / 256, 256>>>(emb);
    kpack_w  <<<(CCH * WELT + 255) / 256, 256>>>(w0, w1, w2, w3, w4);
    k1_dots  <<<dim3(NBH, NCZ), 128, K1_SMEM_BYTES>>>(tokens);
    k1_reduce<<<(SLC + 255) / 256, 256>>>();
    k2_branch<<<dim3(HTOK / 256, 5), 256>>>(b0, b1, b2, b3, b4);
    k3_head  <<<1, 32>>>(lin_w, lin_b, out);
}